// round 11
// baseline (speedup 1.0000x reference)
#include <cuda_runtime.h>
#include <cuda_fp16.h>
#include <math.h>
#include <stdint.h>

// Problem constants: N rows up to 100000, MUL=128, x row = 512 floats.
#define MAXN 100000
#define SQ2F 1.41421356237309515f

// Scratch (allocation-free rule: __device__ globals). fp16 for GEMM-facing data.
__device__ __half g_scal [(size_t)MAXN * 384];
__device__ __half g_h    [(size_t)MAXN * 384];
__device__ __half g_gates[(size_t)MAXN * 256];   // only vector gates (cols 384:640 of G2)
__device__ __half g_vg   [(size_t)MAXN * 256 * 3];
__device__ __half g_outs [(size_t)MAXN * 128];
__device__ __half g_outv [(size_t)MAXN * 128 * 3];
// Packed (transposed to [N,K] K-major, fp16) weights.
__device__ __half g_w1p[384 * 384];
__device__ __half g_w2p[640 * 384];
__device__ __half g_wsp[128 * 384];
__device__ __half g_wvp[128 * 256];

__device__ __forceinline__ float silu_f(float v) { return v / (1.0f + expf(-v)); }

__device__ __forceinline__ uint32_t smem_u32(const void* p) {
    uint32_t a;
    asm("{ .reg .u64 t; cvta.to.shared.u64 t, %1; cvt.u32.u64 %0, t; }" : "=r"(a) : "l"(p));
    return a;
}

__device__ __forceinline__ void cp16(uint32_t dst, const void* src, int sz) {
    asm volatile("cp.async.cg.shared.global [%0], [%1], 16, %2;"
                 :: "r"(dst), "l"(src), "r"(sz) : "memory");
}

#define MMA16816(d, a0, a1, a2, a3, b0, b1)                                  \
    asm volatile(                                                            \
        "mma.sync.aligned.m16n8k16.row.col.f32.f16.f16.f32 "                 \
        "{%0,%1,%2,%3}, {%4,%5,%6,%7}, {%8,%9}, {%0,%1,%2,%3};\n"            \
        : "+f"((d)[0]), "+f"((d)[1]), "+f"((d)[2]), "+f"((d)[3])             \
        : "r"(a0), "r"(a1), "r"(a2), "r"(a3), "r"(b0), "r"(b1))

// ---------------------------------------------------------------------------
// Weight pack: Wp[n*K + k] = fp16(W[k*ldw + n]); keep first Ncols columns.
// ---------------------------------------------------------------------------
__global__ void pack_w_kernel(const float* __restrict__ W, __half* __restrict__ Wp,
                              int K, int Ncols, int ldw) {
    int idx = blockIdx.x * blockDim.x + threadIdx.x;
    if (idx >= Ncols * K) return;
    int n = idx / K;
    int k = idx - n * K;
    Wp[idx] = __float2half(W[(size_t)k * ldw + n]);
}

// ---------------------------------------------------------------------------
// K1: scal[n,384] = [s, s*s, |v|^2] in fp16.
// ---------------------------------------------------------------------------
__global__ void prep_scal_kernel(const float* __restrict__ x, __half* __restrict__ scal, int n) {
    int idx = blockIdx.x * blockDim.x + threadIdx.x;
    if (idx >= n * 128) return;
    int row = idx >> 7;
    int u = idx & 127;
    const float* xr = x + (size_t)row * 512;
    float s  = xr[u];
    float v0 = xr[128 + u * 3 + 0];
    float v1 = xr[128 + u * 3 + 1];
    float v2 = xr[128 + u * 3 + 2];
    __half* sr = scal + (size_t)row * 384;
    sr[u]       = __float2half(s);
    sr[128 + u] = __float2half(s * s);
    sr[256 + u] = __float2half(v0 * v0 + v1 * v1 + v2 * v2);
}

// ---------------------------------------------------------------------------
// FP16 mma.sync GEMM (fp32 acc), pipelined.
//   C[M, ncols*128] = A[M,K] @ Bp^T, Bp packed [N,K] row-major.
// Block 256x128, BK=32, 3-stage cp.async, 256 threads = 8 warps
// (4M x 2N grid of 64x64 warp tiles). Single __syncthreads per iteration
// (trailing barrier is redundant: next iteration's leading barrier orders
// fragment consumption before any cp.async overwrite of that stage).
// MODE 0: plain store to C. MODE 1: silu then store.
// MODE 2: G2 fusion — colBase<384: scal *= silu(acc) in place;
//                     colBase>=384: gates[row*256 + col-384] = silu(acc).
// ---------------------------------------------------------------------------
#define A_TILE_HALVES 10240         // 256*40
#define B_TILE_HALVES 5120          // 128*40
#define STAGE_HALVES 15360          // A tile + B tile
#define GEMM_SMEM (3 * STAGE_HALVES * 2)   // 92160 bytes

template <int MODE, typename OT>
__global__ __launch_bounds__(256) void gemm_fp16_kernel(
    const __half* __restrict__ A, int lda, long long bsA,
    const __half* __restrict__ Bp,
    OT* __restrict__ C, int ldc, long long bsC,
    int M, int K,
    __half* __restrict__ scal)
{
    extern __shared__ __half smh[];
    const uint32_t sb = smem_u32(smh);

    A += (size_t)blockIdx.z * bsA;
    C += (size_t)blockIdx.z * bsC;

    const int tid  = threadIdx.x;
    const int w    = tid >> 5;
    const int lane = tid & 31;
    const int g    = lane >> 2;
    const int tg   = lane & 3;
    const int wm   = (w & 3) * 64;     // 4 M-warps
    const int wn   = (w >> 2) * 64;    // 2 N-warps
    const int rowBase = blockIdx.y * 256;
    const int colBase = blockIdx.x * 128;
    const int T = K >> 5;

    auto load_stage = [&](int s, int kt) {
        const int k0 = kt << 5;
        const uint32_t ab = sb + (uint32_t)(s * STAGE_HALVES) * 2u;
        const uint32_t bb = ab + (uint32_t)A_TILE_HALVES * 2u;
        // A tile: 256 rows x 4 chunks = 1024 chunks, 4 per thread.
#pragma unroll
        for (int i = 0; i < 4; i++) {
            int flat = i * 256 + tid;
            int r = flat >> 2;
            int c = flat & 3;
            uint32_t so = (uint32_t)(r * 40 + c * 8) * 2u;
            int gr = rowBase + r;
            const __half* srcA = A + (size_t)(gr < M ? gr : 0) * lda + k0 + c * 8;
            cp16(ab + so, srcA, gr < M ? 16 : 0);
        }
        // B tile: 128 rows x 4 chunks = 512 chunks, 2 per thread.
#pragma unroll
        for (int i = 0; i < 2; i++) {
            int flat = i * 256 + tid;
            int r = flat >> 2;
            int c = flat & 3;
            uint32_t so = (uint32_t)(r * 40 + c * 8) * 2u;
            cp16(bb + so, Bp + (size_t)(colBase + r) * K + k0 + c * 8, 16);
        }
        asm volatile("cp.async.commit_group;" ::: "memory");
    };

    float acc[4][8][4];
#pragma unroll
    for (int mt = 0; mt < 4; mt++)
#pragma unroll
        for (int nt = 0; nt < 8; nt++)
#pragma unroll
            for (int i = 0; i < 4; i++) acc[mt][nt][i] = 0.0f;

    load_stage(0, 0);
    load_stage(1, 1);

    for (int kt = 0; kt < T; kt++) {
        const int s = kt % 3;
        if (kt + 1 < T) asm volatile("cp.async.wait_group 1;" ::: "memory");
        else            asm volatile("cp.async.wait_group 0;" ::: "memory");
        __syncthreads();
        if (kt + 2 < T) load_stage((kt + 2) % 3, kt + 2);

        const uint32_t* aw = reinterpret_cast<const uint32_t*>(smh + s * STAGE_HALVES);
        const uint32_t* bw = aw + (A_TILE_HALVES / 2);
#pragma unroll
        for (int kf = 0; kf < 2; kf++) {
            const int kb = kf * 8;
            unsigned a[4][4], b[8][2];
#pragma unroll
            for (int mt = 0; mt < 4; mt++) {
                const uint32_t* ap = aw + (wm + mt * 16 + g) * 20 + kb + tg;
                a[mt][0] = ap[0];
                a[mt][1] = ap[8 * 20];
                a[mt][2] = ap[4];
                a[mt][3] = ap[8 * 20 + 4];
            }
#pragma unroll
            for (int nt = 0; nt < 8; nt++) {
                const uint32_t* bp = bw + (wn + nt * 8 + g) * 20 + kb + tg;
                b[nt][0] = bp[0];
                b[nt][1] = bp[4];
            }
#pragma unroll
            for (int mt = 0; mt < 4; mt++)
#pragma unroll
                for (int nt = 0; nt < 8; nt++)
                    MMA16816(acc[mt][nt], a[mt][0], a[mt][1], a[mt][2], a[mt][3],
                             b[nt][0], b[nt][1]);
        }
        // trailing __syncthreads removed (see header comment)
    }

    // ---- Epilogue ----
#pragma unroll
    for (int mt = 0; mt < 4; mt++) {
        int r0 = rowBase + wm + mt * 16 + g;
#pragma unroll
        for (int nt = 0; nt < 8; nt++) {
            int c0 = colBase + wn + nt * 8 + 2 * tg;
            float2 lo = make_float2(acc[mt][nt][0], acc[mt][nt][1]);
            float2 hi = make_float2(acc[mt][nt][2], acc[mt][nt][3]);
            if (MODE >= 1) {
                lo.x = silu_f(lo.x); lo.y = silu_f(lo.y);
                hi.x = silu_f(hi.x); hi.y = silu_f(hi.y);
            }
            if (MODE == 2) {
                if (colBase < 384) {
                    if (r0 < M) {
                        __half2* p = reinterpret_cast<__half2*>(scal + (size_t)r0 * 384 + c0);
                        float2 o = __half22float2(*p);
                        *p = __floats2half2_rn(o.x * lo.x, o.y * lo.y);
                    }
                    if (r0 + 8 < M) {
                        __half2* p = reinterpret_cast<__half2*>(scal + (size_t)(r0 + 8) * 384 + c0);
                        float2 o = __half22float2(*p);
                        *p = __floats2half2_rn(o.x * hi.x, o.y * hi.y);
                    }
                } else {
                    int cg = c0 - 384;
                    if (r0 < M)
                        *reinterpret_cast<__half2*>(C + (size_t)r0 * 256 + cg) =
                            __float22half2_rn(lo);
                    if (r0 + 8 < M)
                        *reinterpret_cast<__half2*>(C + (size_t)(r0 + 8) * 256 + cg) =
                            __float22half2_rn(hi);
                }
            } else {
                if (r0 < M) {
                    OT* cr = C + (size_t)r0 * ldc + c0;
                    if (sizeof(OT) == 2) *reinterpret_cast<__half2*>(cr) = __float22half2_rn(lo);
                    else                 *reinterpret_cast<float2*>(cr) = lo;
                }
                if (r0 + 8 < M) {
                    OT* cr = C + (size_t)(r0 + 8) * ldc + c0;
                    if (sizeof(OT) == 2) *reinterpret_cast<__half2*>(cr) = __float22half2_rn(hi);
                    else                 *reinterpret_cast<float2*>(cr) = hi;
                }
            }
        }
    }
}

// ---------------------------------------------------------------------------
// K4: build gated vec planes from x and vector gates (gates is [n,256]).
// ---------------------------------------------------------------------------
__global__ void gate_prep_kernel(const float* __restrict__ x, const __half* __restrict__ gates,
                                 __half* __restrict__ vg, int n) {
    int idx = blockIdx.x * blockDim.x + threadIdx.x;
    if (idx >= n * 128) return;
    int row = idx >> 7;
    int u = idx & 127;
    const __half* gr = gates + (size_t)row * 256;
    const float* xr = x + (size_t)row * 512;
    float s  = xr[u];
    float g1 = __half2float(gr[u]);
    float c2 = SQ2F * s * __half2float(gr[128 + u]);
#pragma unroll
    for (int i = 0; i < 3; i++) {
        float vi = xr[128 + u * 3 + i];
        __half* vgp = vg + ((size_t)i * n + row) * 256;
        vgp[u]       = __float2half(vi * g1);
        vgp[128 + u] = __float2half(vi * c2);
    }
}

// ---------------------------------------------------------------------------
// K7: residuals + scalar layernorm + vector RMS norm, write output [n,512].
// outs/outv are fp16; all norm math fp32.
// ---------------------------------------------------------------------------
__global__ void finalize_kernel(const float* __restrict__ x, const __half* __restrict__ outs,
                                const __half* __restrict__ outv, float* __restrict__ out, int n) {
    int gw = (int)((blockIdx.x * blockDim.x + threadIdx.x) >> 5);
    int lane = threadIdx.x & 31;
    if (gw >= n) return;
    const float* xr = x + (size_t)gw * 512;
    float* orow = out + (size_t)gw * 512;

    float so[4];
    float sum = 0.f;
#pragma unroll
    for (int t = 0; t < 4; t++) {
        int u = lane + 32 * t;
        so[t] = __half2float(outs[(size_t)gw * 128 + u]) + xr[u];
        sum += so[t];
    }
#pragma unroll
    for (int o = 16; o > 0; o >>= 1) sum += __shfl_xor_sync(0xffffffffu, sum, o);
    float mean = sum * (1.0f / 128.0f);
    float ssum = 0.f;
#pragma unroll
    for (int t = 0; t < 4; t++) {
        so[t] -= mean;
        ssum += so[t] * so[t];
    }
#pragma unroll
    for (int o = 16; o > 0; o >>= 1) ssum += __shfl_xor_sync(0xffffffffu, ssum, o);
    float inv = 1.0f / (sqrtf(ssum * (1.0f / 128.0f)) + 1e-6f);
#pragma unroll
    for (int t = 0; t < 4; t++) orow[lane + 32 * t] = so[t] * inv;

    float vo[4][3];
    float vs = 0.f;
#pragma unroll
    for (int t = 0; t < 4; t++) {
        int u = lane + 32 * t;
#pragma unroll
        for (int i = 0; i < 3; i++) {
            vo[t][i] = __half2float(outv[((size_t)i * n + gw) * 128 + u]) + xr[128 + u * 3 + i];
            vs += vo[t][i] * vo[t][i];
        }
    }
#pragma unroll
    for (int o = 16; o > 0; o >>= 1) vs += __shfl_xor_sync(0xffffffffu, vs, o);
    float vinv = 1.0f / (sqrtf(vs * (1.0f / 128.0f)) + 1e-6f);
#pragma unroll
    for (int t = 0; t < 4; t++) {
        int u = lane + 32 * t;
#pragma unroll
        for (int i = 0; i < 3; i++)
            orow[128 + u * 3 + i] = vo[t][i] * vinv;
    }
}

// ---------------------------------------------------------------------------
extern "C" void kernel_launch(void* const* d_in, const int* in_sizes, int n_in,
                              void* d_out, int out_size) {
    const float* x  = (const float*)d_in[0];
    const float* W1 = (const float*)d_in[1];   // [384,384]
    const float* W2 = (const float*)d_in[2];   // [384,768] (cols 640:768 dead)
    const float* Ws = (const float*)d_in[3];   // [384,128]
    const float* Wv = (const float*)d_in[4];   // [256,128]
    float* out = (float*)d_out;
    int n = in_sizes[0] / 512;

    __half *scal, *h, *gates, *vg, *outs, *outv, *w1p, *w2p, *wsp, *wvp;
    cudaGetSymbolAddress((void**)&scal,  g_scal);
    cudaGetSymbolAddress((void**)&h,     g_h);
    cudaGetSymbolAddress((void**)&gates, g_gates);
    cudaGetSymbolAddress((void**)&vg,    g_vg);
    cudaGetSymbolAddress((void**)&outs,  g_outs);
    cudaGetSymbolAddress((void**)&outv,  g_outv);
    cudaGetSymbolAddress((void**)&w1p,   g_w1p);
    cudaGetSymbolAddress((void**)&w2p,   g_w2p);
    cudaGetSymbolAddress((void**)&wsp,   g_wsp);
    cudaGetSymbolAddress((void**)&wvp,   g_wvp);

    cudaFuncSetAttribute((const void*)gemm_fp16_kernel<1, __half>,
                         cudaFuncAttributeMaxDynamicSharedMemorySize, GEMM_SMEM);
    cudaFuncSetAttribute((const void*)gemm_fp16_kernel<2, __half>,
                         cudaFuncAttributeMaxDynamicSharedMemorySize, GEMM_SMEM);
    cudaFuncSetAttribute((const void*)gemm_fp16_kernel<0, __half>,
                         cudaFuncAttributeMaxDynamicSharedMemorySize, GEMM_SMEM);

    int mblocks = (n + 255) / 256;

    // Pack weights -> [N,K] K-major fp16.
    pack_w_kernel<<<(384 * 384 + 255) / 256, 256>>>(W1, w1p, 384, 384, 384);
    pack_w_kernel<<<(640 * 384 + 255) / 256, 256>>>(W2, w2p, 384, 640, 768);
    pack_w_kernel<<<(128 * 384 + 255) / 256, 256>>>(Ws, wsp, 384, 128, 128);
    pack_w_kernel<<<(128 * 256 + 255) / 256, 256>>>(Wv, wvp, 256, 128, 128);

    // K1: scal features (fp16)
    prep_scal_kernel<<<(n * 128 + 255) / 256, 256>>>(x, scal, n);

    // G1: h = silu(scal @ W1) -> fp16
    dim3 g1(3, mblocks, 1);
    gemm_fp16_kernel<1, __half><<<g1, 256, GEMM_SMEM>>>(
        scal, 384, 0LL, w1p, h, 384, 0LL, n, 384, nullptr);

    // G2 fused: col tiles 0-2 gate scal in place; tiles 3-4 write gates[n,256]
    dim3 g2(5, mblocks, 1);
    gemm_fp16_kernel<2, __half><<<g2, 256, GEMM_SMEM>>>(
        h, 384, 0LL, w2p, gates, 256, 0LL, n, 384, scal);

    // K4: build vg planes from x and vector gates
    gate_prep_kernel<<<(n * 128 + 255) / 256, 256>>>(x, gates, vg, n);

    // G5: outs = scal_gated @ Ws -> fp16
    dim3 g5(1, mblocks, 1);
    gemm_fp16_kernel<0, __half><<<g5, 256, GEMM_SMEM>>>(
        scal, 384, 0LL, wsp, outs, 128, 0LL, n, 384, nullptr);

    // G6: outv_i = vg_i @ Wv (3 planes over z) -> fp16
    dim3 g6(1, mblocks, 3);
    gemm_fp16_kernel<0, __half><<<g6, 256, GEMM_SMEM>>>(
        vg, 256, (long long)n * 256, wvp, outv, 128, (long long)n * 128, n, 256, nullptr);

    // K7: residual + norms + output
    finalize_kernel<<<(n + 7) / 8, 256>>>(x, outs, outv, out, n);
}

// round 12
// speedup vs baseline: 1.2125x; 1.2125x over previous
#include <cuda_runtime.h>
#include <cuda_fp16.h>
#include <math.h>
#include <stdint.h>

// Problem constants: N rows up to 100000, MUL=128, x row = 512 floats.
#define MAXN 100000
#define SQ2F 1.41421356237309515f

// Scratch (allocation-free rule: __device__ globals). fp16 for GEMM-facing data.
__device__ __half g_scal [(size_t)MAXN * 384];
__device__ __half g_h    [(size_t)MAXN * 384];
__device__ __half g_gates[(size_t)MAXN * 256];   // only vector gates (cols 384:640 of G2)
__device__ __half g_vg   [(size_t)MAXN * 256 * 3];
__device__ __half g_outs [(size_t)MAXN * 128];
__device__ __half g_outv [(size_t)MAXN * 128 * 3];
// Packed (transposed to [N,K] K-major, fp16) weights.
__device__ __half g_w1p[384 * 384];
__device__ __half g_w2p[640 * 384];
__device__ __half g_wsp[128 * 384];
__device__ __half g_wvp[128 * 256];

__device__ __forceinline__ float silu_f(float v) { return v / (1.0f + expf(-v)); }

__device__ __forceinline__ uint32_t smem_u32(const void* p) {
    uint32_t a;
    asm("{ .reg .u64 t; cvta.to.shared.u64 t, %1; cvt.u32.u64 %0, t; }" : "=r"(a) : "l"(p));
    return a;
}

__device__ __forceinline__ void cp16(uint32_t dst, const void* src, int sz) {
    asm volatile("cp.async.cg.shared.global [%0], [%1], 16, %2;"
                 :: "r"(dst), "l"(src), "r"(sz) : "memory");
}

#define MMA16816(d, a0, a1, a2, a3, b0, b1)                                  \
    asm volatile(                                                            \
        "mma.sync.aligned.m16n8k16.row.col.f32.f16.f16.f32 "                 \
        "{%0,%1,%2,%3}, {%4,%5,%6,%7}, {%8,%9}, {%0,%1,%2,%3};\n"            \
        : "+f"((d)[0]), "+f"((d)[1]), "+f"((d)[2]), "+f"((d)[3])             \
        : "r"(a0), "r"(a1), "r"(a2), "r"(a3), "r"(b0), "r"(b1))

// ---------------------------------------------------------------------------
// Weight pack: Wp[n*K + k] = fp16(W[k*ldw + n]); keep first Ncols columns.
// ---------------------------------------------------------------------------
__global__ void pack_w_kernel(const float* __restrict__ W, __half* __restrict__ Wp,
                              int K, int Ncols, int ldw) {
    int idx = blockIdx.x * blockDim.x + threadIdx.x;
    if (idx >= Ncols * K) return;
    int n = idx / K;
    int k = idx - n * K;
    Wp[idx] = __float2half(W[(size_t)k * ldw + n]);
}

// ---------------------------------------------------------------------------
// K1: scal[n,384] = [s, s*s, |v|^2] in fp16.
// ---------------------------------------------------------------------------
__global__ void prep_scal_kernel(const float* __restrict__ x, __half* __restrict__ scal, int n) {
    int idx = blockIdx.x * blockDim.x + threadIdx.x;
    if (idx >= n * 128) return;
    int row = idx >> 7;
    int u = idx & 127;
    const float* xr = x + (size_t)row * 512;
    float s  = xr[u];
    float v0 = xr[128 + u * 3 + 0];
    float v1 = xr[128 + u * 3 + 1];
    float v2 = xr[128 + u * 3 + 2];
    __half* sr = scal + (size_t)row * 384;
    sr[u]       = __float2half(s);
    sr[128 + u] = __float2half(s * s);
    sr[256 + u] = __float2half(v0 * v0 + v1 * v1 + v2 * v2);
}

// ---------------------------------------------------------------------------
// FP16 mma.sync GEMM (fp32 acc), pipelined (R10 mainloop; 3 CTAs/SM probe).
//   C[M, ncols*128] = A[M,K] @ Bp^T, Bp packed [N,K] row-major.
// Block 128x128, BK=32, 3-stage cp.async, 4 warps (2x2 of 64x64 warp tiles).
// MODE 0: plain store to C. MODE 1: silu then store.
// MODE 2: G2 fusion — colBase<384: scal *= silu(acc) in place;
//                     colBase>=384: gates[row*256 + col-384] = silu(acc).
// ---------------------------------------------------------------------------
#define TILE_HALVES 5120            // 128*40
#define STAGE_HALVES 10240          // A tile + B tile
#define GEMM_SMEM (3 * STAGE_HALVES * 2)   // 61440 bytes

template <int MODE, typename OT>
__global__ __launch_bounds__(128, 3) void gemm_fp16_kernel(
    const __half* __restrict__ A, int lda, long long bsA,
    const __half* __restrict__ Bp,
    OT* __restrict__ C, int ldc, long long bsC,
    int M, int K,
    __half* __restrict__ scal)
{
    extern __shared__ __half smh[];
    const uint32_t sb = smem_u32(smh);

    A += (size_t)blockIdx.z * bsA;
    C += (size_t)blockIdx.z * bsC;

    const int tid  = threadIdx.x;
    const int w    = tid >> 5;
    const int lane = tid & 31;
    const int g    = lane >> 2;
    const int tg   = lane & 3;
    const int wm   = (w & 1) * 64;
    const int wn   = (w >> 1) * 64;
    const int rowBase = blockIdx.y * 128;
    const int colBase = blockIdx.x * 128;
    const int T = K >> 5;

    auto load_stage = [&](int s, int kt) {
        const int k0 = kt << 5;
        const uint32_t ab = sb + (uint32_t)(s * STAGE_HALVES) * 2u;
        const uint32_t bb = ab + TILE_HALVES * 2u;
#pragma unroll
        for (int i = 0; i < 4; i++) {
            int flat = i * 128 + tid;
            int r = flat >> 2;
            int c = flat & 3;
            uint32_t so = (uint32_t)(r * 40 + c * 8) * 2u;
            int gr = rowBase + r;
            const __half* srcA = A + (size_t)(gr < M ? gr : 0) * lda + k0 + c * 8;
            cp16(ab + so, srcA, gr < M ? 16 : 0);
            const __half* srcB = Bp + (size_t)(colBase + r) * K + k0 + c * 8;
            cp16(bb + so, srcB, 16);
        }
        asm volatile("cp.async.commit_group;" ::: "memory");
    };

    float acc[4][8][4];
#pragma unroll
    for (int mt = 0; mt < 4; mt++)
#pragma unroll
        for (int nt = 0; nt < 8; nt++)
#pragma unroll
            for (int i = 0; i < 4; i++) acc[mt][nt][i] = 0.0f;

    load_stage(0, 0);
    load_stage(1, 1);

    for (int kt = 0; kt < T; kt++) {
        const int s = kt % 3;
        if (kt + 1 < T) asm volatile("cp.async.wait_group 1;" ::: "memory");
        else            asm volatile("cp.async.wait_group 0;" ::: "memory");
        __syncthreads();
        if (kt + 2 < T) load_stage((kt + 2) % 3, kt + 2);

        const uint32_t* aw = reinterpret_cast<const uint32_t*>(smh + s * STAGE_HALVES);
        const uint32_t* bw = aw + (TILE_HALVES / 2);
#pragma unroll
        for (int kf = 0; kf < 2; kf++) {
            const int kb = kf * 8;
            unsigned a[4][4], b[8][2];
#pragma unroll
            for (int mt = 0; mt < 4; mt++) {
                const uint32_t* ap = aw + (wm + mt * 16 + g) * 20 + kb + tg;
                a[mt][0] = ap[0];
                a[mt][1] = ap[8 * 20];
                a[mt][2] = ap[4];
                a[mt][3] = ap[8 * 20 + 4];
            }
#pragma unroll
            for (int nt = 0; nt < 8; nt++) {
                const uint32_t* bp = bw + (wn + nt * 8 + g) * 20 + kb + tg;
                b[nt][0] = bp[0];
                b[nt][1] = bp[4];
            }
#pragma unroll
            for (int mt = 0; mt < 4; mt++)
#pragma unroll
                for (int nt = 0; nt < 8; nt++)
                    MMA16816(acc[mt][nt], a[mt][0], a[mt][1], a[mt][2], a[mt][3],
                             b[nt][0], b[nt][1]);
        }
        __syncthreads();
    }

    // ---- Epilogue ----
#pragma unroll
    for (int mt = 0; mt < 4; mt++) {
        int r0 = rowBase + wm + mt * 16 + g;
#pragma unroll
        for (int nt = 0; nt < 8; nt++) {
            int c0 = colBase + wn + nt * 8 + 2 * tg;
            float2 lo = make_float2(acc[mt][nt][0], acc[mt][nt][1]);
            float2 hi = make_float2(acc[mt][nt][2], acc[mt][nt][3]);
            if (MODE >= 1) {
                lo.x = silu_f(lo.x); lo.y = silu_f(lo.y);
                hi.x = silu_f(hi.x); hi.y = silu_f(hi.y);
            }
            if (MODE == 2) {
                if (colBase < 384) {
                    if (r0 < M) {
                        __half2* p = reinterpret_cast<__half2*>(scal + (size_t)r0 * 384 + c0);
                        float2 o = __half22float2(*p);
                        *p = __floats2half2_rn(o.x * lo.x, o.y * lo.y);
                    }
                    if (r0 + 8 < M) {
                        __half2* p = reinterpret_cast<__half2*>(scal + (size_t)(r0 + 8) * 384 + c0);
                        float2 o = __half22float2(*p);
                        *p = __floats2half2_rn(o.x * hi.x, o.y * hi.y);
                    }
                } else {
                    int cg = c0 - 384;
                    if (r0 < M)
                        *reinterpret_cast<__half2*>(C + (size_t)r0 * 256 + cg) =
                            __float22half2_rn(lo);
                    if (r0 + 8 < M)
                        *reinterpret_cast<__half2*>(C + (size_t)(r0 + 8) * 256 + cg) =
                            __float22half2_rn(hi);
                }
            } else {
                if (r0 < M) {
                    OT* cr = C + (size_t)r0 * ldc + c0;
                    if (sizeof(OT) == 2) *reinterpret_cast<__half2*>(cr) = __float22half2_rn(lo);
                    else                 *reinterpret_cast<float2*>(cr) = lo;
                }
                if (r0 + 8 < M) {
                    OT* cr = C + (size_t)(r0 + 8) * ldc + c0;
                    if (sizeof(OT) == 2) *reinterpret_cast<__half2*>(cr) = __float22half2_rn(hi);
                    else                 *reinterpret_cast<float2*>(cr) = hi;
                }
            }
        }
    }
}

// ---------------------------------------------------------------------------
// K4: build gated vec planes from x and vector gates (gates is [n,256]).
// ---------------------------------------------------------------------------
__global__ void gate_prep_kernel(const float* __restrict__ x, const __half* __restrict__ gates,
                                 __half* __restrict__ vg, int n) {
    int idx = blockIdx.x * blockDim.x + threadIdx.x;
    if (idx >= n * 128) return;
    int row = idx >> 7;
    int u = idx & 127;
    const __half* gr = gates + (size_t)row * 256;
    const float* xr = x + (size_t)row * 512;
    float s  = xr[u];
    float g1 = __half2float(gr[u]);
    float c2 = SQ2F * s * __half2float(gr[128 + u]);
#pragma unroll
    for (int i = 0; i < 3; i++) {
        float vi = xr[128 + u * 3 + i];
        __half* vgp = vg + ((size_t)i * n + row) * 256;
        vgp[u]       = __float2half(vi * g1);
        vgp[128 + u] = __float2half(vi * c2);
    }
}

// ---------------------------------------------------------------------------
// K7: residuals + scalar layernorm + vector RMS norm, write output [n,512].
// outs/outv are fp16; all norm math fp32.
// ---------------------------------------------------------------------------
__global__ void finalize_kernel(const float* __restrict__ x, const __half* __restrict__ outs,
                                const __half* __restrict__ outv, float* __restrict__ out, int n) {
    int gw = (int)((blockIdx.x * blockDim.x + threadIdx.x) >> 5);
    int lane = threadIdx.x & 31;
    if (gw >= n) return;
    const float* xr = x + (size_t)gw * 512;
    float* orow = out + (size_t)gw * 512;

    float so[4];
    float sum = 0.f;
#pragma unroll
    for (int t = 0; t < 4; t++) {
        int u = lane + 32 * t;
        so[t] = __half2float(outs[(size_t)gw * 128 + u]) + xr[u];
        sum += so[t];
    }
#pragma unroll
    for (int o = 16; o > 0; o >>= 1) sum += __shfl_xor_sync(0xffffffffu, sum, o);
    float mean = sum * (1.0f / 128.0f);
    float ssum = 0.f;
#pragma unroll
    for (int t = 0; t < 4; t++) {
        so[t] -= mean;
        ssum += so[t] * so[t];
    }
#pragma unroll
    for (int o = 16; o > 0; o >>= 1) ssum += __shfl_xor_sync(0xffffffffu, ssum, o);
    float inv = 1.0f / (sqrtf(ssum * (1.0f / 128.0f)) + 1e-6f);
#pragma unroll
    for (int t = 0; t < 4; t++) orow[lane + 32 * t] = so[t] * inv;

    float vo[4][3];
    float vs = 0.f;
#pragma unroll
    for (int t = 0; t < 4; t++) {
        int u = lane + 32 * t;
#pragma unroll
        for (int i = 0; i < 3; i++) {
            vo[t][i] = __half2float(outv[((size_t)i * n + gw) * 128 + u]) + xr[128 + u * 3 + i];
            vs += vo[t][i] * vo[t][i];
        }
    }
#pragma unroll
    for (int o = 16; o > 0; o >>= 1) vs += __shfl_xor_sync(0xffffffffu, vs, o);
    float vinv = 1.0f / (sqrtf(vs * (1.0f / 128.0f)) + 1e-6f);
#pragma unroll
    for (int t = 0; t < 4; t++) {
        int u = lane + 32 * t;
#pragma unroll
        for (int i = 0; i < 3; i++)
            orow[128 + u * 3 + i] = vo[t][i] * vinv;
    }
}

// ---------------------------------------------------------------------------
extern "C" void kernel_launch(void* const* d_in, const int* in_sizes, int n_in,
                              void* d_out, int out_size) {
    const float* x  = (const float*)d_in[0];
    const float* W1 = (const float*)d_in[1];   // [384,384]
    const float* W2 = (const float*)d_in[2];   // [384,768] (cols 640:768 dead)
    const float* Ws = (const float*)d_in[3];   // [384,128]
    const float* Wv = (const float*)d_in[4];   // [256,128]
    float* out = (float*)d_out;
    int n = in_sizes[0] / 512;

    __half *scal, *h, *gates, *vg, *outs, *outv, *w1p, *w2p, *wsp, *wvp;
    cudaGetSymbolAddress((void**)&scal,  g_scal);
    cudaGetSymbolAddress((void**)&h,     g_h);
    cudaGetSymbolAddress((void**)&gates, g_gates);
    cudaGetSymbolAddress((void**)&vg,    g_vg);
    cudaGetSymbolAddress((void**)&outs,  g_outs);
    cudaGetSymbolAddress((void**)&outv,  g_outv);
    cudaGetSymbolAddress((void**)&w1p,   g_w1p);
    cudaGetSymbolAddress((void**)&w2p,   g_w2p);
    cudaGetSymbolAddress((void**)&wsp,   g_wsp);
    cudaGetSymbolAddress((void**)&wvp,   g_wvp);

    cudaFuncSetAttribute((const void*)gemm_fp16_kernel<1, __half>,
                         cudaFuncAttributeMaxDynamicSharedMemorySize, GEMM_SMEM);
    cudaFuncSetAttribute((const void*)gemm_fp16_kernel<2, __half>,
                         cudaFuncAttributeMaxDynamicSharedMemorySize, GEMM_SMEM);
    cudaFuncSetAttribute((const void*)gemm_fp16_kernel<0, __half>,
                         cudaFuncAttributeMaxDynamicSharedMemorySize, GEMM_SMEM);

    int mblocks = (n + 127) / 128;

    // Pack weights -> [N,K] K-major fp16.
    pack_w_kernel<<<(384 * 384 + 255) / 256, 256>>>(W1, w1p, 384, 384, 384);
    pack_w_kernel<<<(640 * 384 + 255) / 256, 256>>>(W2, w2p, 384, 640, 768);
    pack_w_kernel<<<(128 * 384 + 255) / 256, 256>>>(Ws, wsp, 384, 128, 128);
    pack_w_kernel<<<(128 * 256 + 255) / 256, 256>>>(Wv, wvp, 256, 128, 128);

    // K1: scal features (fp16)
    prep_scal_kernel<<<(n * 128 + 255) / 256, 256>>>(x, scal, n);

    // G1: h = silu(scal @ W1) -> fp16
    dim3 g1(3, mblocks, 1);
    gemm_fp16_kernel<1, __half><<<g1, 128, GEMM_SMEM>>>(
        scal, 384, 0LL, w1p, h, 384, 0LL, n, 384, nullptr);

    // G2 fused: col tiles 0-2 gate scal in place; tiles 3-4 write gates[n,256]
    dim3 g2(5, mblocks, 1);
    gemm_fp16_kernel<2, __half><<<g2, 128, GEMM_SMEM>>>(
        h, 384, 0LL, w2p, gates, 256, 0LL, n, 384, scal);

    // K4: build vg planes from x and vector gates
    gate_prep_kernel<<<(n * 128 + 255) / 256, 256>>>(x, gates, vg, n);

    // G5: outs = scal_gated @ Ws -> fp16
    dim3 g5(1, mblocks, 1);
    gemm_fp16_kernel<0, __half><<<g5, 128, GEMM_SMEM>>>(
        scal, 384, 0LL, wsp, outs, 128, 0LL, n, 384, nullptr);

    // G6: outv_i = vg_i @ Wv (3 planes over z) -> fp16
    dim3 g6(1, mblocks, 3);
    gemm_fp16_kernel<0, __half><<<g6, 128, GEMM_SMEM>>>(
        vg, 256, (long long)n * 256, wvp, outv, 128, (long long)n * 128, n, 256, nullptr);

    // K7: residual + norms + output
    finalize_kernel<<<(n + 7) / 8, 256>>>(x, outs, outv, out, n);
}

// round 13
// speedup vs baseline: 1.2347x; 1.0183x over previous
#include <cuda_runtime.h>
#include <cuda_fp16.h>
#include <math.h>
#include <stdint.h>

// Problem constants: N rows up to 100000, MUL=128, x row = 512 floats.
#define MAXN 100000
#define SQ2F 1.41421356237309515f

// Scratch (allocation-free rule: __device__ globals). fp16 for GEMM-facing data.
__device__ __half g_scal [(size_t)MAXN * 384];
__device__ __half g_h    [(size_t)MAXN * 384];
__device__ __half g_gates[(size_t)MAXN * 256];   // vector gates (cols 384:640 of G2)
__device__ __half g_vg   [(size_t)MAXN * 256 * 3];
__device__ __half g_outs [(size_t)MAXN * 128];
__device__ __half g_outv [(size_t)MAXN * 128 * 3];
__device__ __half g_sh   [(size_t)MAXN * 128];       // fp16 copy of s
__device__ __half g_vp   [(size_t)MAXN * 128 * 3];   // fp16 v planes (coalesced)
// Packed (transposed to [N,K] K-major, fp16) weights.
__device__ __half g_w1p[384 * 384];
__device__ __half g_w2p[640 * 384];
__device__ __half g_wsp[128 * 384];
__device__ __half g_wvp[128 * 256];

__device__ __forceinline__ float silu_f(float v) { return v / (1.0f + expf(-v)); }

__device__ __forceinline__ uint32_t smem_u32(const void* p) {
    uint32_t a;
    asm("{ .reg .u64 t; cvta.to.shared.u64 t, %1; cvt.u32.u64 %0, t; }" : "=r"(a) : "l"(p));
    return a;
}

__device__ __forceinline__ void cp16(uint32_t dst, const void* src, int sz) {
    asm volatile("cp.async.cg.shared.global [%0], [%1], 16, %2;"
                 :: "r"(dst), "l"(src), "r"(sz) : "memory");
}

#define MMA16816(d, a0, a1, a2, a3, b0, b1)                                  \
    asm volatile(                                                            \
        "mma.sync.aligned.m16n8k16.row.col.f32.f16.f16.f32 "                 \
        "{%0,%1,%2,%3}, {%4,%5,%6,%7}, {%8,%9}, {%0,%1,%2,%3};\n"            \
        : "+f"((d)[0]), "+f"((d)[1]), "+f"((d)[2]), "+f"((d)[3])             \
        : "r"(a0), "r"(a1), "r"(a2), "r"(a3), "r"(b0), "r"(b1))

// ---------------------------------------------------------------------------
// Fused weight pack: all 4 weights -> [N,K] K-major fp16, one launch.
// ---------------------------------------------------------------------------
#define S1 (384 * 384)
#define S2 (S1 + 640 * 384)
#define S3 (S2 + 128 * 384)
#define S4 (S3 + 128 * 256)
__global__ void pack_all_kernel(const float* __restrict__ W1, const float* __restrict__ W2,
                                const float* __restrict__ Ws, const float* __restrict__ Wv,
                                __half* __restrict__ w1p, __half* __restrict__ w2p,
                                __half* __restrict__ wsp, __half* __restrict__ wvp) {
    int idx = blockIdx.x * blockDim.x + threadIdx.x;
    if (idx < S1) {
        int n = idx / 384, k = idx - n * 384;
        w1p[idx] = __float2half(W1[(size_t)k * 384 + n]);
    } else if (idx < S2) {
        int j = idx - S1;
        int n = j / 384, k = j - n * 384;
        w2p[j] = __float2half(W2[(size_t)k * 768 + n]);
    } else if (idx < S3) {
        int j = idx - S2;
        int n = j / 384, k = j - n * 384;
        wsp[j] = __float2half(Ws[(size_t)k * 128 + n]);
    } else if (idx < S4) {
        int j = idx - S3;
        int n = j / 256, k = j - n * 256;
        wvp[j] = __float2half(Wv[(size_t)k * 128 + n]);
    }
}

// ---------------------------------------------------------------------------
// K1: scal[n,384] = [s, s*s, |v|^2] fp16; also sh[n,128]=s and v planes
// vp[3][n,128] (coalesced fp16 copies — the ONLY strided x-gather).
// ---------------------------------------------------------------------------
__global__ void prep_kernel(const float* __restrict__ x, __half* __restrict__ scal,
                            __half* __restrict__ sh, __half* __restrict__ vp, int n) {
    int idx = blockIdx.x * blockDim.x + threadIdx.x;
    if (idx >= n * 128) return;
    int row = idx >> 7;
    int u = idx & 127;
    const float* xr = x + (size_t)row * 512;
    float s  = xr[u];
    float v0 = xr[128 + u * 3 + 0];
    float v1 = xr[128 + u * 3 + 1];
    float v2 = xr[128 + u * 3 + 2];
    __half* sr = scal + (size_t)row * 384;
    sr[u]       = __float2half(s);
    sr[128 + u] = __float2half(s * s);
    sr[256 + u] = __float2half(v0 * v0 + v1 * v1 + v2 * v2);
    sh[idx] = __float2half(s);
    vp[(size_t)0 * n * 128 + idx] = __float2half(v0);
    vp[(size_t)1 * n * 128 + idx] = __float2half(v1);
    vp[(size_t)2 * n * 128 + idx] = __float2half(v2);
}

// ---------------------------------------------------------------------------
// FP16 mma.sync GEMM (fp32 acc), pipelined, 3 CTAs/SM.
// Block 128x128, BK=32, 3-stage cp.async, 4 warps (2x2 of 64x64 warp tiles).
// MODE 0: plain store. MODE 1: silu store.
// MODE 2: G2 fusion — colBase<384: scal *= silu(acc); else gates = silu(acc).
// MODE 3: merged G5/G6 — z==0: A=Ain,B=Bin,K=Kin,C=Cout;
//                        z>0:  A=A2+(z-1)*n*256 (K=256), B=B2, C=C2+(z-1)*n*128.
// ---------------------------------------------------------------------------
#define TILE_HALVES 5120            // 128*40
#define STAGE_HALVES 10240          // A tile + B tile
#define GEMM_SMEM (3 * STAGE_HALVES * 2)   // 61440 bytes

template <int MODE, typename OT>
__global__ __launch_bounds__(128, 3) void gemm_fp16_kernel(
    const __half* __restrict__ A, int lda, long long bsA,
    const __half* __restrict__ Bp,
    OT* __restrict__ C, int ldc, long long bsC,
    int M, int K,
    __half* __restrict__ scal,
    const __half* __restrict__ A2, const __half* __restrict__ B2, OT* __restrict__ C2)
{
    extern __shared__ __half smh[];
    const uint32_t sb = smem_u32(smh);

    if (MODE == 3) {
        int z = blockIdx.z;
        if (z > 0) {
            A = A2 + (size_t)(z - 1) * M * 256;
            lda = 256;
            K = 256;
            Bp = B2;
            C = C2 + (size_t)(z - 1) * M * 128;
        }
    } else {
        A += (size_t)blockIdx.z * bsA;
        C += (size_t)blockIdx.z * bsC;
    }

    const int tid  = threadIdx.x;
    const int w    = tid >> 5;
    const int lane = tid & 31;
    const int g    = lane >> 2;
    const int tg   = lane & 3;
    const int wm   = (w & 1) * 64;
    const int wn   = (w >> 1) * 64;
    const int rowBase = blockIdx.y * 128;
    const int colBase = blockIdx.x * 128;
    const int T = K >> 5;

    auto load_stage = [&](int s, int kt) {
        const int k0 = kt << 5;
        const uint32_t ab = sb + (uint32_t)(s * STAGE_HALVES) * 2u;
        const uint32_t bb = ab + TILE_HALVES * 2u;
#pragma unroll
        for (int i = 0; i < 4; i++) {
            int flat = i * 128 + tid;
            int r = flat >> 2;
            int c = flat & 3;
            uint32_t so = (uint32_t)(r * 40 + c * 8) * 2u;
            int gr = rowBase + r;
            const __half* srcA = A + (size_t)(gr < M ? gr : 0) * lda + k0 + c * 8;
            cp16(ab + so, srcA, gr < M ? 16 : 0);
            const __half* srcB = Bp + (size_t)(colBase + r) * K + k0 + c * 8;
            cp16(bb + so, srcB, 16);
        }
        asm volatile("cp.async.commit_group;" ::: "memory");
    };

    float acc[4][8][4];
#pragma unroll
    for (int mt = 0; mt < 4; mt++)
#pragma unroll
        for (int nt = 0; nt < 8; nt++)
#pragma unroll
            for (int i = 0; i < 4; i++) acc[mt][nt][i] = 0.0f;

    load_stage(0, 0);
    load_stage(1, 1);

    for (int kt = 0; kt < T; kt++) {
        const int s = kt % 3;
        if (kt + 1 < T) asm volatile("cp.async.wait_group 1;" ::: "memory");
        else            asm volatile("cp.async.wait_group 0;" ::: "memory");
        __syncthreads();
        if (kt + 2 < T) load_stage((kt + 2) % 3, kt + 2);

        const uint32_t* aw = reinterpret_cast<const uint32_t*>(smh + s * STAGE_HALVES);
        const uint32_t* bw = aw + (TILE_HALVES / 2);
#pragma unroll
        for (int kf = 0; kf < 2; kf++) {
            const int kb = kf * 8;
            unsigned a[4][4], b[8][2];
#pragma unroll
            for (int mt = 0; mt < 4; mt++) {
                const uint32_t* ap = aw + (wm + mt * 16 + g) * 20 + kb + tg;
                a[mt][0] = ap[0];
                a[mt][1] = ap[8 * 20];
                a[mt][2] = ap[4];
                a[mt][3] = ap[8 * 20 + 4];
            }
#pragma unroll
            for (int nt = 0; nt < 8; nt++) {
                const uint32_t* bp = bw + (wn + nt * 8 + g) * 20 + kb + tg;
                b[nt][0] = bp[0];
                b[nt][1] = bp[4];
            }
#pragma unroll
            for (int mt = 0; mt < 4; mt++)
#pragma unroll
                for (int nt = 0; nt < 8; nt++)
                    MMA16816(acc[mt][nt], a[mt][0], a[mt][1], a[mt][2], a[mt][3],
                             b[nt][0], b[nt][1]);
        }
        __syncthreads();
    }

    // ---- Epilogue ----
#pragma unroll
    for (int mt = 0; mt < 4; mt++) {
        int r0 = rowBase + wm + mt * 16 + g;
#pragma unroll
        for (int nt = 0; nt < 8; nt++) {
            int c0 = colBase + wn + nt * 8 + 2 * tg;
            float2 lo = make_float2(acc[mt][nt][0], acc[mt][nt][1]);
            float2 hi = make_float2(acc[mt][nt][2], acc[mt][nt][3]);
            if (MODE == 1 || MODE == 2) {
                lo.x = silu_f(lo.x); lo.y = silu_f(lo.y);
                hi.x = silu_f(hi.x); hi.y = silu_f(hi.y);
            }
            if (MODE == 2) {
                if (colBase < 384) {
                    if (r0 < M) {
                        __half2* p = reinterpret_cast<__half2*>(scal + (size_t)r0 * 384 + c0);
                        float2 o = __half22float2(*p);
                        *p = __floats2half2_rn(o.x * lo.x, o.y * lo.y);
                    }
                    if (r0 + 8 < M) {
                        __half2* p = reinterpret_cast<__half2*>(scal + (size_t)(r0 + 8) * 384 + c0);
                        float2 o = __half22float2(*p);
                        *p = __floats2half2_rn(o.x * hi.x, o.y * hi.y);
                    }
                } else {
                    int cg = c0 - 384;
                    if (r0 < M)
                        *reinterpret_cast<__half2*>(C + (size_t)r0 * 256 + cg) =
                            __float22half2_rn(lo);
                    if (r0 + 8 < M)
                        *reinterpret_cast<__half2*>(C + (size_t)(r0 + 8) * 256 + cg) =
                            __float22half2_rn(hi);
                }
            } else {
                if (r0 < M) {
                    OT* cr = C + (size_t)r0 * ldc + c0;
                    if (sizeof(OT) == 2) *reinterpret_cast<__half2*>(cr) = __float22half2_rn(lo);
                    else                 *reinterpret_cast<float2*>(cr) = lo;
                }
                if (r0 + 8 < M) {
                    OT* cr = C + (size_t)(r0 + 8) * ldc + c0;
                    if (sizeof(OT) == 2) *reinterpret_cast<__half2*>(cr) = __float22half2_rn(hi);
                    else                 *reinterpret_cast<float2*>(cr) = hi;
                }
            }
        }
    }
}

// ---------------------------------------------------------------------------
// K4: build gated vec planes — fully coalesced (sh/vp/gates/vg all planar).
// ---------------------------------------------------------------------------
__global__ void gate_prep_kernel(const __half* __restrict__ sh, const __half* __restrict__ gates,
                                 const __half* __restrict__ vp, __half* __restrict__ vg, int n) {
    int idx = blockIdx.x * blockDim.x + threadIdx.x;
    if (idx >= n * 128) return;
    int row = idx >> 7;
    int u = idx & 127;
    const __half* gr = gates + (size_t)row * 256;
    float s  = __half2float(sh[idx]);
    float g1 = __half2float(gr[u]);
    float c2 = SQ2F * s * __half2float(gr[128 + u]);
#pragma unroll
    for (int i = 0; i < 3; i++) {
        float vi = __half2float(vp[(size_t)i * n * 128 + idx]);
        __half* vgp = vg + ((size_t)i * n + row) * 256;
        vgp[u]       = __float2half(vi * g1);
        vgp[128 + u] = __float2half(vi * c2);
    }
}

// ---------------------------------------------------------------------------
// K7: residuals + scalar layernorm + vector RMS norm, write output [n,512].
// Residuals from fp16 sh/vp (coalesced); all norm math fp32.
// ---------------------------------------------------------------------------
__global__ void finalize_kernel(const __half* __restrict__ sh, const __half* __restrict__ vp,
                                const __half* __restrict__ outs, const __half* __restrict__ outv,
                                float* __restrict__ out, int n) {
    int gw = (int)((blockIdx.x * blockDim.x + threadIdx.x) >> 5);
    int lane = threadIdx.x & 31;
    if (gw >= n) return;
    float* orow = out + (size_t)gw * 512;

    float so[4];
    float sum = 0.f;
#pragma unroll
    for (int t = 0; t < 4; t++) {
        int u = lane + 32 * t;
        so[t] = __half2float(outs[(size_t)gw * 128 + u]) + __half2float(sh[(size_t)gw * 128 + u]);
        sum += so[t];
    }
#pragma unroll
    for (int o = 16; o > 0; o >>= 1) sum += __shfl_xor_sync(0xffffffffu, sum, o);
    float mean = sum * (1.0f / 128.0f);
    float ssum = 0.f;
#pragma unroll
    for (int t = 0; t < 4; t++) {
        so[t] -= mean;
        ssum += so[t] * so[t];
    }
#pragma unroll
    for (int o = 16; o > 0; o >>= 1) ssum += __shfl_xor_sync(0xffffffffu, ssum, o);
    float inv = 1.0f / (sqrtf(ssum * (1.0f / 128.0f)) + 1e-6f);
#pragma unroll
    for (int t = 0; t < 4; t++) orow[lane + 32 * t] = so[t] * inv;

    float vo[4][3];
    float vs = 0.f;
#pragma unroll
    for (int t = 0; t < 4; t++) {
        int u = lane + 32 * t;
#pragma unroll
        for (int i = 0; i < 3; i++) {
            vo[t][i] = __half2float(outv[((size_t)i * n + gw) * 128 + u])
                     + __half2float(vp[((size_t)i * n + gw) * 128 + u]);
            vs += vo[t][i] * vo[t][i];
        }
    }
#pragma unroll
    for (int o = 16; o > 0; o >>= 1) vs += __shfl_xor_sync(0xffffffffu, vs, o);
    float vinv = 1.0f / (sqrtf(vs * (1.0f / 128.0f)) + 1e-6f);
#pragma unroll
    for (int t = 0; t < 4; t++) {
        int u = lane + 32 * t;
#pragma unroll
        for (int i = 0; i < 3; i++)
            orow[128 + u * 3 + i] = vo[t][i] * vinv;
    }
}

// ---------------------------------------------------------------------------
extern "C" void kernel_launch(void* const* d_in, const int* in_sizes, int n_in,
                              void* d_out, int out_size) {
    const float* x  = (const float*)d_in[0];
    const float* W1 = (const float*)d_in[1];   // [384,384]
    const float* W2 = (const float*)d_in[2];   // [384,768] (cols 640:768 dead)
    const float* Ws = (const float*)d_in[3];   // [384,128]
    const float* Wv = (const float*)d_in[4];   // [256,128]
    float* out = (float*)d_out;
    int n = in_sizes[0] / 512;

    __half *scal, *h, *gates, *vg, *outs, *outv, *sh, *vp, *w1p, *w2p, *wsp, *wvp;
    cudaGetSymbolAddress((void**)&scal,  g_scal);
    cudaGetSymbolAddress((void**)&h,     g_h);
    cudaGetSymbolAddress((void**)&gates, g_gates);
    cudaGetSymbolAddress((void**)&vg,    g_vg);
    cudaGetSymbolAddress((void**)&outs,  g_outs);
    cudaGetSymbolAddress((void**)&outv,  g_outv);
    cudaGetSymbolAddress((void**)&sh,    g_sh);
    cudaGetSymbolAddress((void**)&vp,    g_vp);
    cudaGetSymbolAddress((void**)&w1p,   g_w1p);
    cudaGetSymbolAddress((void**)&w2p,   g_w2p);
    cudaGetSymbolAddress((void**)&wsp,   g_wsp);
    cudaGetSymbolAddress((void**)&wvp,   g_wvp);

    cudaFuncSetAttribute((const void*)gemm_fp16_kernel<1, __half>,
                         cudaFuncAttributeMaxDynamicSharedMemorySize, GEMM_SMEM);
    cudaFuncSetAttribute((const void*)gemm_fp16_kernel<2, __half>,
                         cudaFuncAttributeMaxDynamicSharedMemorySize, GEMM_SMEM);
    cudaFuncSetAttribute((const void*)gemm_fp16_kernel<3, __half>,
                         cudaFuncAttributeMaxDynamicSharedMemorySize, GEMM_SMEM);

    int mblocks = (n + 127) / 128;

    // Fused weight pack (1 launch).
    pack_all_kernel<<<(S4 + 255) / 256, 256>>>(W1, W2, Ws, Wv, w1p, w2p, wsp, wvp);

    // K1: scal features + fp16 s / v planes
    prep_kernel<<<(n * 128 + 255) / 256, 256>>>(x, scal, sh, vp, n);

    // G1: h = silu(scal @ W1) -> fp16
    dim3 g1(3, mblocks, 1);
    gemm_fp16_kernel<1, __half><<<g1, 128, GEMM_SMEM>>>(
        scal, 384, 0LL, w1p, h, 384, 0LL, n, 384, nullptr, nullptr, nullptr, nullptr);

    // G2 fused: col tiles 0-2 gate scal in place; tiles 3-4 write gates[n,256]
    dim3 g2(5, mblocks, 1);
    gemm_fp16_kernel<2, __half><<<g2, 128, GEMM_SMEM>>>(
        h, 384, 0LL, w2p, gates, 256, 0LL, n, 384, scal, nullptr, nullptr, nullptr);

    // K4: build vg planes (fully coalesced)
    gate_prep_kernel<<<(n * 128 + 255) / 256, 256>>>(sh, gates, vp, vg, n);

    // G5+G6 merged: z=0 -> outs = scal@Ws (K=384); z=1..3 -> outv_i = vg_i@Wv (K=256)
    dim3 g56(1, mblocks, 4);
    gemm_fp16_kernel<3, __half><<<g56, 128, GEMM_SMEM>>>(
        scal, 384, 0LL, wsp, outs, 128, 0LL, n, 384, nullptr, vg, wvp, outv);

    // K7: residual + norms + output
    finalize_kernel<<<(n + 7) / 8, 256>>>(sh, vp, outs, outv, out, n);
}

// round 14
// speedup vs baseline: 1.2934x; 1.0476x over previous
#include <cuda_runtime.h>
#include <cuda_fp16.h>
#include <math.h>
#include <stdint.h>

// Problem constants: N rows up to 100000, MUL=128, x row = 512 floats.
#define MAXN 100000
#define SQ2F 1.41421356237309515f

// Scratch (allocation-free rule: __device__ globals). fp16 for GEMM-facing data.
__device__ __half g_scal [(size_t)MAXN * 384];
__device__ __half g_h    [(size_t)MAXN * 384];
__device__ __half g_gates[(size_t)MAXN * 256];   // vector gates (cols 384:640 of G2)
__device__ __half g_vg   [(size_t)MAXN * 256 * 3];
__device__ __half g_outs [(size_t)MAXN * 128];
__device__ __half g_outv [(size_t)MAXN * 128 * 3];
__device__ __half g_sh   [(size_t)MAXN * 128];       // fp16 copy of s
__device__ __half g_vp   [(size_t)MAXN * 128 * 3];   // fp16 v planes (coalesced)
// Packed (transposed to [N,K] K-major, fp16) weights.
__device__ __half g_w1p[384 * 384];
__device__ __half g_w2p[640 * 384];
__device__ __half g_wsp[128 * 384];
__device__ __half g_wvp[128 * 256];

__device__ __forceinline__ float silu_f(float v) { return v / (1.0f + expf(-v)); }

__device__ __forceinline__ uint32_t smem_u32(const void* p) {
    uint32_t a;
    asm("{ .reg .u64 t; cvta.to.shared.u64 t, %1; cvt.u32.u64 %0, t; }" : "=r"(a) : "l"(p));
    return a;
}

__device__ __forceinline__ void cp16(uint32_t dst, const void* src, int sz) {
    asm volatile("cp.async.cg.shared.global [%0], [%1], 16, %2;"
                 :: "r"(dst), "l"(src), "r"(sz) : "memory");
}

#define MMA16816(d, a0, a1, a2, a3, b0, b1)                                  \
    asm volatile(                                                            \
        "mma.sync.aligned.m16n8k16.row.col.f32.f16.f16.f32 "                 \
        "{%0,%1,%2,%3}, {%4,%5,%6,%7}, {%8,%9}, {%0,%1,%2,%3};\n"            \
        : "+f"((d)[0]), "+f"((d)[1]), "+f"((d)[2]), "+f"((d)[3])             \
        : "r"(a0), "r"(a1), "r"(a2), "r"(a3), "r"(b0), "r"(b1))

// ---------------------------------------------------------------------------
// Fused weight pack: all 4 weights -> [N,K] K-major fp16, one launch.
// ---------------------------------------------------------------------------
#define S1 (384 * 384)
#define S2 (S1 + 640 * 384)
#define S3 (S2 + 128 * 384)
#define S4 (S3 + 128 * 256)
__global__ void pack_all_kernel(const float* __restrict__ W1, const float* __restrict__ W2,
                                const float* __restrict__ Ws, const float* __restrict__ Wv,
                                __half* __restrict__ w1p, __half* __restrict__ w2p,
                                __half* __restrict__ wsp, __half* __restrict__ wvp) {
    int idx = blockIdx.x * blockDim.x + threadIdx.x;
    if (idx < S1) {
        int n = idx / 384, k = idx - n * 384;
        w1p[idx] = __float2half(W1[(size_t)k * 384 + n]);
    } else if (idx < S2) {
        int j = idx - S1;
        int n = j / 384, k = j - n * 384;
        w2p[j] = __float2half(W2[(size_t)k * 768 + n]);
    } else if (idx < S3) {
        int j = idx - S2;
        int n = j / 384, k = j - n * 384;
        wsp[j] = __float2half(Ws[(size_t)k * 128 + n]);
    } else if (idx < S4) {
        int j = idx - S3;
        int n = j / 256, k = j - n * 256;
        wvp[j] = __float2half(Wv[(size_t)k * 128 + n]);
    }
}

// ---------------------------------------------------------------------------
// K1: scal[n,384] = [s, s*s, |v|^2] fp16; also sh[n,128]=s and v planes
// vp[3][n,128] (coalesced fp16 copies — the ONLY strided x-gather).
// ---------------------------------------------------------------------------
__global__ void prep_kernel(const float* __restrict__ x, __half* __restrict__ scal,
                            __half* __restrict__ sh, __half* __restrict__ vp, int n) {
    int idx = blockIdx.x * blockDim.x + threadIdx.x;
    if (idx >= n * 128) return;
    int row = idx >> 7;
    int u = idx & 127;
    const float* xr = x + (size_t)row * 512;
    float s  = xr[u];
    float v0 = xr[128 + u * 3 + 0];
    float v1 = xr[128 + u * 3 + 1];
    float v2 = xr[128 + u * 3 + 2];
    __half* sr = scal + (size_t)row * 384;
    sr[u]       = __float2half(s);
    sr[128 + u] = __float2half(s * s);
    sr[256 + u] = __float2half(v0 * v0 + v1 * v1 + v2 * v2);
    sh[idx] = __float2half(s);
    vp[(size_t)0 * n * 128 + idx] = __float2half(v0);
    vp[(size_t)1 * n * 128 + idx] = __float2half(v1);
    vp[(size_t)2 * n * 128 + idx] = __float2half(v2);
}

// ---------------------------------------------------------------------------
// FP16 mma.sync GEMM (fp32 acc), pipelined, 4 CTAs/SM (occupancy probe).
// Block 64x128, BK=32, 3-stage cp.async, 4 warps (2Mx2N of 32x64 warp tiles).
// MODE 0: plain store. MODE 1: silu store.
// MODE 2: G2 fusion — colBase<384: scal *= silu(acc); else gates = silu(acc).
// MODE 3: merged G5/G6 — z==0: A,Bp,K,C as passed;
//                        z>0:  A=A2+(z-1)*M*256 (K=256), B=B2, C=C2+(z-1)*M*128.
// ---------------------------------------------------------------------------
#define A_TILE_HALVES 2560          // 64*40
#define B_TILE_HALVES 5120          // 128*40
#define STAGE_HALVES 7680           // A + B
#define GEMM_SMEM (3 * STAGE_HALVES * 2)   // 46080 bytes

template <int MODE, typename OT>
__global__ __launch_bounds__(128, 4) void gemm_fp16_kernel(
    const __half* __restrict__ A, int lda, long long bsA,
    const __half* __restrict__ Bp,
    OT* __restrict__ C, int ldc, long long bsC,
    int M, int K,
    __half* __restrict__ scal,
    const __half* __restrict__ A2, const __half* __restrict__ B2, OT* __restrict__ C2)
{
    extern __shared__ __half smh[];
    const uint32_t sb = smem_u32(smh);

    if (MODE == 3) {
        int z = blockIdx.z;
        if (z > 0) {
            A = A2 + (size_t)(z - 1) * M * 256;
            lda = 256;
            K = 256;
            Bp = B2;
            C = C2 + (size_t)(z - 1) * M * 128;
        }
    } else {
        A += (size_t)blockIdx.z * bsA;
        C += (size_t)blockIdx.z * bsC;
    }

    const int tid  = threadIdx.x;
    const int w    = tid >> 5;
    const int lane = tid & 31;
    const int g    = lane >> 2;
    const int tg   = lane & 3;
    const int wm   = (w & 1) * 32;     // 2 M-warps of 32 rows
    const int wn   = (w >> 1) * 64;    // 2 N-warps of 64 cols
    const int rowBase = blockIdx.y * 64;
    const int colBase = blockIdx.x * 128;
    const int T = K >> 5;

    auto load_stage = [&](int s, int kt) {
        const int k0 = kt << 5;
        const uint32_t ab = sb + (uint32_t)(s * STAGE_HALVES) * 2u;
        const uint32_t bb = ab + A_TILE_HALVES * 2u;
        // A tile: 64 rows x 4 chunks = 256 -> 2 per thread
#pragma unroll
        for (int i = 0; i < 2; i++) {
            int flat = i * 128 + tid;
            int r = flat >> 2;
            int c = flat & 3;
            uint32_t so = (uint32_t)(r * 40 + c * 8) * 2u;
            int gr = rowBase + r;
            const __half* srcA = A + (size_t)(gr < M ? gr : 0) * lda + k0 + c * 8;
            cp16(ab + so, srcA, gr < M ? 16 : 0);
        }
        // B tile: 128 rows x 4 chunks = 512 -> 4 per thread
#pragma unroll
        for (int i = 0; i < 4; i++) {
            int flat = i * 128 + tid;
            int r = flat >> 2;
            int c = flat & 3;
            uint32_t so = (uint32_t)(r * 40 + c * 8) * 2u;
            cp16(bb + so, Bp + (size_t)(colBase + r) * K + k0 + c * 8, 16);
        }
        asm volatile("cp.async.commit_group;" ::: "memory");
    };

    float acc[2][8][4];
#pragma unroll
    for (int mt = 0; mt < 2; mt++)
#pragma unroll
        for (int nt = 0; nt < 8; nt++)
#pragma unroll
            for (int i = 0; i < 4; i++) acc[mt][nt][i] = 0.0f;

    load_stage(0, 0);
    load_stage(1, 1);

    for (int kt = 0; kt < T; kt++) {
        const int s = kt % 3;
        if (kt + 1 < T) asm volatile("cp.async.wait_group 1;" ::: "memory");
        else            asm volatile("cp.async.wait_group 0;" ::: "memory");
        __syncthreads();
        if (kt + 2 < T) load_stage((kt + 2) % 3, kt + 2);

        const uint32_t* aw = reinterpret_cast<const uint32_t*>(smh + s * STAGE_HALVES);
        const uint32_t* bw = aw + (A_TILE_HALVES / 2);
#pragma unroll
        for (int kf = 0; kf < 2; kf++) {
            const int kb = kf * 8;
            unsigned a[2][4], b[8][2];
#pragma unroll
            for (int mt = 0; mt < 2; mt++) {
                const uint32_t* ap = aw + (wm + mt * 16 + g) * 20 + kb + tg;
                a[mt][0] = ap[0];
                a[mt][1] = ap[8 * 20];
                a[mt][2] = ap[4];
                a[mt][3] = ap[8 * 20 + 4];
            }
#pragma unroll
            for (int nt = 0; nt < 8; nt++) {
                const uint32_t* bp = bw + (wn + nt * 8 + g) * 20 + kb + tg;
                b[nt][0] = bp[0];
                b[nt][1] = bp[4];
            }
#pragma unroll
            for (int mt = 0; mt < 2; mt++)
#pragma unroll
                for (int nt = 0; nt < 8; nt++)
                    MMA16816(acc[mt][nt], a[mt][0], a[mt][1], a[mt][2], a[mt][3],
                             b[nt][0], b[nt][1]);
        }
        __syncthreads();
    }

    // ---- Epilogue ----
#pragma unroll
    for (int mt = 0; mt < 2; mt++) {
        int r0 = rowBase + wm + mt * 16 + g;
#pragma unroll
        for (int nt = 0; nt < 8; nt++) {
            int c0 = colBase + wn + nt * 8 + 2 * tg;
            float2 lo = make_float2(acc[mt][nt][0], acc[mt][nt][1]);
            float2 hi = make_float2(acc[mt][nt][2], acc[mt][nt][3]);
            if (MODE == 1 || MODE == 2) {
                lo.x = silu_f(lo.x); lo.y = silu_f(lo.y);
                hi.x = silu_f(hi.x); hi.y = silu_f(hi.y);
            }
            if (MODE == 2) {
                if (colBase < 384) {
                    if (r0 < M) {
                        __half2* p = reinterpret_cast<__half2*>(scal + (size_t)r0 * 384 + c0);
                        float2 o = __half22float2(*p);
                        *p = __floats2half2_rn(o.x * lo.x, o.y * lo.y);
                    }
                    if (r0 + 8 < M) {
                        __half2* p = reinterpret_cast<__half2*>(scal + (size_t)(r0 + 8) * 384 + c0);
                        float2 o = __half22float2(*p);
                        *p = __floats2half2_rn(o.x * hi.x, o.y * hi.y);
                    }
                } else {
                    int cg = c0 - 384;
                    if (r0 < M)
                        *reinterpret_cast<__half2*>(C + (size_t)r0 * 256 + cg) =
                            __float22half2_rn(lo);
                    if (r0 + 8 < M)
                        *reinterpret_cast<__half2*>(C + (size_t)(r0 + 8) * 256 + cg) =
                            __float22half2_rn(hi);
                }
            } else {
                if (r0 < M) {
                    OT* cr = C + (size_t)r0 * ldc + c0;
                    if (sizeof(OT) == 2) *reinterpret_cast<__half2*>(cr) = __float22half2_rn(lo);
                    else                 *reinterpret_cast<float2*>(cr) = lo;
                }
                if (r0 + 8 < M) {
                    OT* cr = C + (size_t)(r0 + 8) * ldc + c0;
                    if (sizeof(OT) == 2) *reinterpret_cast<__half2*>(cr) = __float22half2_rn(hi);
                    else                 *reinterpret_cast<float2*>(cr) = hi;
                }
            }
        }
    }
}

// ---------------------------------------------------------------------------
// K4: build gated vec planes — fully coalesced (sh/vp/gates/vg all planar).
// ---------------------------------------------------------------------------
__global__ void gate_prep_kernel(const __half* __restrict__ sh, const __half* __restrict__ gates,
                                 const __half* __restrict__ vp, __half* __restrict__ vg, int n) {
    int idx = blockIdx.x * blockDim.x + threadIdx.x;
    if (idx >= n * 128) return;
    int row = idx >> 7;
    int u = idx & 127;
    const __half* gr = gates + (size_t)row * 256;
    float s  = __half2float(sh[idx]);
    float g1 = __half2float(gr[u]);
    float c2 = SQ2F * s * __half2float(gr[128 + u]);
#pragma unroll
    for (int i = 0; i < 3; i++) {
        float vi = __half2float(vp[(size_t)i * n * 128 + idx]);
        __half* vgp = vg + ((size_t)i * n + row) * 256;
        vgp[u]       = __float2half(vi * g1);
        vgp[128 + u] = __float2half(vi * c2);
    }
}

// ---------------------------------------------------------------------------
// K7: residuals + scalar layernorm + vector RMS norm, write output [n,512].
// ---------------------------------------------------------------------------
__global__ void finalize_kernel(const __half* __restrict__ sh, const __half* __restrict__ vp,
                                const __half* __restrict__ outs, const __half* __restrict__ outv,
                                float* __restrict__ out, int n) {
    int gw = (int)((blockIdx.x * blockDim.x + threadIdx.x) >> 5);
    int lane = threadIdx.x & 31;
    if (gw >= n) return;
    float* orow = out + (size_t)gw * 512;

    float so[4];
    float sum = 0.f;
#pragma unroll
    for (int t = 0; t < 4; t++) {
        int u = lane + 32 * t;
        so[t] = __half2float(outs[(size_t)gw * 128 + u]) + __half2float(sh[(size_t)gw * 128 + u]);
        sum += so[t];
    }
#pragma unroll
    for (int o = 16; o > 0; o >>= 1) sum += __shfl_xor_sync(0xffffffffu, sum, o);
    float mean = sum * (1.0f / 128.0f);
    float ssum = 0.f;
#pragma unroll
    for (int t = 0; t < 4; t++) {
        so[t] -= mean;
        ssum += so[t] * so[t];
    }
#pragma unroll
    for (int o = 16; o > 0; o >>= 1) ssum += __shfl_xor_sync(0xffffffffu, ssum, o);
    float inv = 1.0f / (sqrtf(ssum * (1.0f / 128.0f)) + 1e-6f);
#pragma unroll
    for (int t = 0; t < 4; t++) orow[lane + 32 * t] = so[t] * inv;

    float vo[4][3];
    float vs = 0.f;
#pragma unroll
    for (int t = 0; t < 4; t++) {
        int u = lane + 32 * t;
#pragma unroll
        for (int i = 0; i < 3; i++) {
            vo[t][i] = __half2float(outv[((size_t)i * n + gw) * 128 + u])
                     + __half2float(vp[((size_t)i * n + gw) * 128 + u]);
            vs += vo[t][i] * vo[t][i];
        }
    }
#pragma unroll
    for (int o = 16; o > 0; o >>= 1) vs += __shfl_xor_sync(0xffffffffu, vs, o);
    float vinv = 1.0f / (sqrtf(vs * (1.0f / 128.0f)) + 1e-6f);
#pragma unroll
    for (int t = 0; t < 4; t++) {
        int u = lane + 32 * t;
#pragma unroll
        for (int i = 0; i < 3; i++)
            orow[128 + u * 3 + i] = vo[t][i] * vinv;
    }
}

// ---------------------------------------------------------------------------
extern "C" void kernel_launch(void* const* d_in, const int* in_sizes, int n_in,
                              void* d_out, int out_size) {
    const float* x  = (const float*)d_in[0];
    const float* W1 = (const float*)d_in[1];   // [384,384]
    const float* W2 = (const float*)d_in[2];   // [384,768] (cols 640:768 dead)
    const float* Ws = (const float*)d_in[3];   // [384,128]
    const float* Wv = (const float*)d_in[4];   // [256,128]
    float* out = (float*)d_out;
    int n = in_sizes[0] / 512;

    __half *scal, *h, *gates, *vg, *outs, *outv, *sh, *vp, *w1p, *w2p, *wsp, *wvp;
    cudaGetSymbolAddress((void**)&scal,  g_scal);
    cudaGetSymbolAddress((void**)&h,     g_h);
    cudaGetSymbolAddress((void**)&gates, g_gates);
    cudaGetSymbolAddress((void**)&vg,    g_vg);
    cudaGetSymbolAddress((void**)&outs,  g_outs);
    cudaGetSymbolAddress((void**)&outv,  g_outv);
    cudaGetSymbolAddress((void**)&sh,    g_sh);
    cudaGetSymbolAddress((void**)&vp,    g_vp);
    cudaGetSymbolAddress((void**)&w1p,   g_w1p);
    cudaGetSymbolAddress((void**)&w2p,   g_w2p);
    cudaGetSymbolAddress((void**)&wsp,   g_wsp);
    cudaGetSymbolAddress((void**)&wvp,   g_wvp);

    cudaFuncSetAttribute((const void*)gemm_fp16_kernel<1, __half>,
                         cudaFuncAttributeMaxDynamicSharedMemorySize, GEMM_SMEM);
    cudaFuncSetAttribute((const void*)gemm_fp16_kernel<2, __half>,
                         cudaFuncAttributeMaxDynamicSharedMemorySize, GEMM_SMEM);
    cudaFuncSetAttribute((const void*)gemm_fp16_kernel<3, __half>,
                         cudaFuncAttributeMaxDynamicSharedMemorySize, GEMM_SMEM);

    int mblocks = (n + 63) / 64;

    // Fused weight pack (1 launch).
    pack_all_kernel<<<(S4 + 255) / 256, 256>>>(W1, W2, Ws, Wv, w1p, w2p, wsp, wvp);

    // K1: scal features + fp16 s / v planes
    prep_kernel<<<(n * 128 + 255) / 256, 256>>>(x, scal, sh, vp, n);

    // G1: h = silu(scal @ W1) -> fp16
    dim3 g1(3, mblocks, 1);
    gemm_fp16_kernel<1, __half><<<g1, 128, GEMM_SMEM>>>(
        scal, 384, 0LL, w1p, h, 384, 0LL, n, 384, nullptr, nullptr, nullptr, nullptr);

    // G2 fused: col tiles 0-2 gate scal in place; tiles 3-4 write gates[n,256]
    dim3 g2(5, mblocks, 1);
    gemm_fp16_kernel<2, __half><<<g2, 128, GEMM_SMEM>>>(
        h, 384, 0LL, w2p, gates, 256, 0LL, n, 384, scal, nullptr, nullptr, nullptr);

    // K4: build vg planes (fully coalesced)
    gate_prep_kernel<<<(n * 128 + 255) / 256, 256>>>(sh, gates, vp, vg, n);

    // G5+G6 merged: z=0 -> outs = scal@Ws (K=384); z=1..3 -> outv_i = vg_i@Wv (K=256)
    dim3 g56(1, mblocks, 4);
    gemm_fp16_kernel<3, __half><<<g56, 128, GEMM_SMEM>>>(
        scal, 384, 0LL, wsp, outs, 128, 0LL, n, 384, nullptr, vg, wvp, outv);

    // K7: residual + norms + output
    finalize_kernel<<<(n + 7) / 8, 256>>>(sh, vp, outs, outv, out, n);
}